// round 6
// baseline (speedup 1.0000x reference)
#include <cuda_runtime.h>

// Triline interpolation:
//   out[b, :] = lerp(x_line, cx) + lerp(y_line, cy) + lerp(z_line, cz)
// B = 1M points, C = 64 channels, N = 512 rows per line.
//
// Layout: 8 threads per point; each thread handles 8 channels (2 x float4).
// All 12 gather loads issued up front for MLP=12. Output stores streamed
// (evict-first) so the 384 KB of hot tables stay resident in L2.

#define C_CH   64
#define N_ROWS 512

__device__ __forceinline__ void stcs4(float* p, float4 v) {
    asm volatile("st.global.cs.v4.f32 [%0], {%1, %2, %3, %4};"
                 :: "l"(p), "f"(v.x), "f"(v.y), "f"(v.z), "f"(v.w) : "memory");
}

__global__ __launch_bounds__(256, 3) void triline_kernel(
    const float* __restrict__ coords,   // [B, 3]
    const float* __restrict__ x_line,   // [N, C]
    const float* __restrict__ y_line,   // [N, C]
    const float* __restrict__ z_line,   // [N, C]
    const float* __restrict__ grid,     // [N]
    float* __restrict__ out,            // [B, C]
    int B)
{
    const int tid = blockIdx.x * blockDim.x + threadIdx.x;
    const int b   = tid >> 3;            // point index (8 threads per point)
    const int cg  = (tid & 7) << 3;      // channel offset (8 channels per thread)
    if (b >= B) return;

    const float g0    = __ldg(grid);
    const float invdx = 1.0f / (__ldg(grid + 1) - g0);

    const float cx = __ldg(coords + 3 * b + 0);
    const float cy = __ldg(coords + 3 * b + 1);
    const float cz = __ldg(coords + 3 * b + 2);

    float px = (cx - g0) * invdx;
    float py = (cy - g0) * invdx;
    float pz = (cz - g0) * invdx;

    int ix = (int)floorf(px); ix = min(max(ix, 0), N_ROWS - 2);
    int iy = (int)floorf(py); iy = min(max(iy, 0), N_ROWS - 2);
    int iz = (int)floorf(pz); iz = min(max(iz, 0), N_ROWS - 2);

    const float wx = px - (float)ix;
    const float wy = py - (float)iy;
    const float wz = pz - (float)iz;

    // Row pointers; row stride is 64 floats = 16 float4s.
    const float4* xr = (const float4*)(x_line + (ix << 6) + cg);
    const float4* yr = (const float4*)(y_line + (iy << 6) + cg);
    const float4* zr = (const float4*)(z_line + (iz << 6) + cg);

    // Issue all 12 gathers before any consumption (MLP = 12).
    const float4 x0a = __ldg(xr);          const float4 x0b = __ldg(xr + 1);
    const float4 x1a = __ldg(xr + 16);     const float4 x1b = __ldg(xr + 17);
    const float4 y0a = __ldg(yr);          const float4 y0b = __ldg(yr + 1);
    const float4 y1a = __ldg(yr + 16);     const float4 y1b = __ldg(yr + 17);
    const float4 z0a = __ldg(zr);          const float4 z0b = __ldg(zr + 1);
    const float4 z1a = __ldg(zr + 16);     const float4 z1b = __ldg(zr + 17);

    float4 ra, rb;
    ra.x = fmaf(wx, x1a.x - x0a.x, x0a.x) + fmaf(wy, y1a.x - y0a.x, y0a.x) + fmaf(wz, z1a.x - z0a.x, z0a.x);
    ra.y = fmaf(wx, x1a.y - x0a.y, x0a.y) + fmaf(wy, y1a.y - y0a.y, y0a.y) + fmaf(wz, z1a.y - z0a.y, z0a.y);
    ra.z = fmaf(wx, x1a.z - x0a.z, x0a.z) + fmaf(wy, y1a.z - y0a.z, y0a.z) + fmaf(wz, z1a.z - z0a.z, z0a.z);
    ra.w = fmaf(wx, x1a.w - x0a.w, x0a.w) + fmaf(wy, y1a.w - y0a.w, y0a.w) + fmaf(wz, z1a.w - z0a.w, z0a.w);

    rb.x = fmaf(wx, x1b.x - x0b.x, x0b.x) + fmaf(wy, y1b.x - y0b.x, y0b.x) + fmaf(wz, z1b.x - z0b.x, z0b.x);
    rb.y = fmaf(wx, x1b.y - x0b.y, x0b.y) + fmaf(wy, y1b.y - y0b.y, y0b.y) + fmaf(wz, z1b.y - z0b.y, z0b.y);
    rb.z = fmaf(wx, x1b.z - x0b.z, x0b.z) + fmaf(wy, y1b.z - y0b.z, y0b.z) + fmaf(wz, z1b.z - z0b.z, z0b.z);
    rb.w = fmaf(wx, x1b.w - x0b.w, x0b.w) + fmaf(wy, y1b.w - y0b.w, y0b.w) + fmaf(wz, z1b.w - z0b.w, z0b.w);

    float* o = out + (size_t)b * C_CH + cg;
    stcs4(o, ra);
    stcs4(o + 4, rb);
}

extern "C" void kernel_launch(void* const* d_in, const int* in_sizes, int n_in,
                              void* d_out, int out_size)
{
    const float* coords = (const float*)d_in[0];
    const float* x_line = (const float*)d_in[1];
    const float* y_line = (const float*)d_in[2];
    const float* z_line = (const float*)d_in[3];
    const float* grid   = (const float*)d_in[4];
    float* out = (float*)d_out;

    const int B = in_sizes[0] / 3;          // 1048576
    const int total_threads = B * 8;        // 8 threads per point
    const int block = 256;
    const int nblocks = (total_threads + block - 1) / block;

    triline_kernel<<<nblocks, block>>>(coords, x_line, y_line, z_line, grid, out, B);
}

// round 7
// speedup vs baseline: 1.2212x; 1.2212x over previous
#include <cuda_runtime.h>

// Triline interpolation, shared-memory table edition.
//   out[b, :] = lerp(x_line, cx) + lerp(y_line, cy) + lerp(z_line, cz)
// B = 1M, C = 64, N = 512.
//
// Each CTA owns ONE 32-channel half of all three tables in SMEM (192 KB)
// and a contiguous chunk of points. Gathers become LDS (29-cyc latency,
// conflict-free) instead of ~234-cyc L2-hit LDGs. Grid = 148 chunks x 2 halves.

#define N_ROWS  512
#define C_CH    64
#define CHALF   32
#define NCHUNK  148
#define BLOCK   1024
#define SMEM_BYTES (3 * N_ROWS * CHALF * 4)   // 192 KB

__global__ __launch_bounds__(BLOCK, 1) void triline_smem_kernel(
    const float* __restrict__ coords,   // [B, 3]
    const float* __restrict__ x_line,   // [N, C]
    const float* __restrict__ y_line,   // [N, C]
    const float* __restrict__ z_line,   // [N, C]
    const float* __restrict__ grid,     // [N]
    float* __restrict__ out,            // [B, C]
    int B, int ptsPer)
{
    extern __shared__ float smem[];     // [3][512][32]
    float* sx = smem;
    float* sy = smem + N_ROWS * CHALF;
    float* sz = smem + 2 * N_ROWS * CHALF;

    const int tIn   = threadIdx.x;
    const int half  = blockIdx.x & 1;          // channel half: 0 or 1
    const int chunk = blockIdx.x >> 1;         // point chunk: 0..147
    const int choff = half * CHALF;

    // ---- Stage this channel-half of all three tables into SMEM ----
    // Each row-half = 32 floats = 8 float4. Total 512*8 = 4096 float4 per table.
    for (int i = tIn; i < N_ROWS * CHALF / 4; i += BLOCK) {
        const int row = i >> 3;                // 8 float4 per row-half
        const int q   = (i & 7) << 2;          // float offset within half
        const int src = row * C_CH + choff + q;
        ((float4*)sx)[i] = *(const float4*)(x_line + src);
        ((float4*)sy)[i] = *(const float4*)(y_line + src);
        ((float4*)sz)[i] = *(const float4*)(z_line + src);
    }

    const float g0    = __ldg(grid);
    const float invdx = 1.0f / (__ldg(grid + 1) - g0);

    __syncthreads();

    // ---- Main loop: 8 threads per point-half, 128 points per iteration ----
    const int lane8  = tIn & 7;                // which float4 of the 32-ch half
    const int c4     = lane8 << 2;
    const int pstart = chunk * ptsPer;
    const int pend   = min(pstart + ptsPer, B);

    for (int p = pstart + (tIn >> 3); p < pend; p += BLOCK / 8) {
        const float cx = __ldg(coords + 3 * p + 0);
        const float cy = __ldg(coords + 3 * p + 1);
        const float cz = __ldg(coords + 3 * p + 2);

        const float px = (cx - g0) * invdx;
        const float py = (cy - g0) * invdx;
        const float pz = (cz - g0) * invdx;

        int ix = (int)floorf(px); ix = min(max(ix, 0), N_ROWS - 2);
        int iy = (int)floorf(py); iy = min(max(iy, 0), N_ROWS - 2);
        int iz = (int)floorf(pz); iz = min(max(iz, 0), N_ROWS - 2);

        const float wx = px - (float)ix;
        const float wy = py - (float)iy;
        const float wz = pz - (float)iz;

        // Six conflict-free LDS.128 gathers from the SMEM tables.
        const float4 x0 = *(const float4*)(sx + ix * CHALF + c4);
        const float4 x1 = *(const float4*)(sx + (ix + 1) * CHALF + c4);
        const float4 y0 = *(const float4*)(sy + iy * CHALF + c4);
        const float4 y1 = *(const float4*)(sy + (iy + 1) * CHALF + c4);
        const float4 z0 = *(const float4*)(sz + iz * CHALF + c4);
        const float4 z1 = *(const float4*)(sz + (iz + 1) * CHALF + c4);

        float4 r;
        r.x = fmaf(wx, x1.x - x0.x, x0.x) + fmaf(wy, y1.x - y0.x, y0.x) + fmaf(wz, z1.x - z0.x, z0.x);
        r.y = fmaf(wx, x1.y - x0.y, x0.y) + fmaf(wy, y1.y - y0.y, y0.y) + fmaf(wz, z1.y - z0.y, z0.y);
        r.z = fmaf(wx, x1.z - x0.z, x0.z) + fmaf(wy, y1.z - y0.z, y0.z) + fmaf(wz, z1.z - z0.z, z0.z);
        r.w = fmaf(wx, x1.w - x0.w, x0.w) + fmaf(wy, y1.w - y0.w, y0.w) + fmaf(wz, z1.w - z0.w, z0.w);

        *(float4*)(out + (size_t)p * C_CH + choff + c4) = r;
    }
}

extern "C" void kernel_launch(void* const* d_in, const int* in_sizes, int n_in,
                              void* d_out, int out_size)
{
    const float* coords = (const float*)d_in[0];
    const float* x_line = (const float*)d_in[1];
    const float* y_line = (const float*)d_in[2];
    const float* z_line = (const float*)d_in[3];
    const float* grid   = (const float*)d_in[4];
    float* out = (float*)d_out;

    const int B = in_sizes[0] / 3;                 // 1048576
    const int ptsPer = (B + NCHUNK - 1) / NCHUNK;  // 7086

    static int smem_set = 0;
    if (!smem_set) {
        cudaFuncSetAttribute(triline_smem_kernel,
                             cudaFuncAttributeMaxDynamicSharedMemorySize, SMEM_BYTES);
        smem_set = 1;
    }

    triline_smem_kernel<<<2 * NCHUNK, BLOCK, SMEM_BYTES>>>(
        coords, x_line, y_line, z_line, grid, out, B, ptsPer);
}